// round 1
// baseline (speedup 1.0000x reference)
#include <cuda_runtime.h>
#include <cuda_bf16.h>
#include <cstdint>

// ---------------------------------------------------------------------------
// ProxyNCALoss on GB300 (sm_103a)
//   loss_b = d_pos[b] + log( exp(-xsq_b - 1) * S_b - exp(-d_pos_b) )
//   S_b    = sum_c exp(2 * dot(x_b, p_hat_c))
// Main cost: M=1024 x N=100000 x K=128 bf16 GEMM (mma.sync) with exp row-sum
// epilogue. Proxies normalized + converted to bf16 once per launch.
// ---------------------------------------------------------------------------

#define C_CLS 100000
#define D_DIM 128
#define B_ROWS 1024

constexpr int BM = 128;
constexpr int BN = 128;
constexpr int BK = 128;
constexpr int NTILES = (C_CLS + BN - 1) / BN;      // 782
constexpr int N_PAD  = NTILES * BN;                // 100096
constexpr int SMEM_PAD = 8;                        // bf16 elements of row pad
constexpr int LDS_A = BK + SMEM_PAD;               // 136
constexpr int SMEM_BYTES = (BM * LDS_A + BN * LDS_A) * 2;  // 69632

// ------------------------- device scratch (no cudaMalloc allowed) ----------
__device__ __nv_bfloat16 g_P[(size_t)N_PAD * D_DIM];   // normalized proxies, bf16 (25.6MB)
__device__ __nv_bfloat16 g_X[B_ROWS * D_DIM];          // xs in bf16
__device__ float g_partial[NTILES][B_ROWS];            // per-ntile row sums (3.2MB)
__device__ float g_dpos[B_ROWS];
__device__ float g_xsq[B_ROWS];
__device__ int   g_is64;

// ------------------------- helpers -----------------------------------------
__device__ __forceinline__ float warp_sum(float v) {
#pragma unroll
    for (int m = 16; m > 0; m >>= 1) v += __shfl_xor_sync(0xFFFFFFFFu, v, m);
    return v;
}

// ------------------------- ys dtype detection (int64 vs int32) -------------
__global__ void detect_kernel(const int* __restrict__ ys32) {
    __shared__ int flag;
    if (threadIdx.x == 0) flag = 1;
    __syncthreads();
    // If underlying dtype is int64 (values < 2^31), every odd int32 word is 0.
    // If int32, odd words are random labels in [0,100000): P(all zero) ~ 0.
    if (ys32[2 * threadIdx.x + 1] != 0) flag = 0;
    __syncthreads();
    if (threadIdx.x == 0) g_is64 = flag;
}

// ------------------------- xs -> bf16 ---------------------------------------
__global__ void convertx_kernel(const float* __restrict__ xs) {
    int i = blockIdx.x * blockDim.x + threadIdx.x;   // 32768 float4 slots
    float4 v = reinterpret_cast<const float4*>(xs)[i];
    __nv_bfloat162 lo = __floats2bfloat162_rn(v.x, v.y);
    __nv_bfloat162 hi = __floats2bfloat162_rn(v.z, v.w);
    reinterpret_cast<__nv_bfloat162*>(g_X)[2 * i]     = lo;
    reinterpret_cast<__nv_bfloat162*>(g_X)[2 * i + 1] = hi;
}

// ------------------------- proxies: L2-normalize + bf16 --------------------
__global__ void normp_kernel(const float* __restrict__ proxies) {
    int warp = (blockIdx.x * blockDim.x + threadIdx.x) >> 5;
    int lane = threadIdx.x & 31;
    if (warp >= N_PAD) return;
    uint2* dst = reinterpret_cast<uint2*>(g_P + (size_t)warp * D_DIM);
    if (warp >= C_CLS) {            // zero-fill pad rows
        uint2 z; z.x = 0u; z.y = 0u;
        dst[lane] = z;
        return;
    }
    float4 v = reinterpret_cast<const float4*>(proxies + (size_t)warp * D_DIM)[lane];
    float sq = v.x * v.x + v.y * v.y + v.z * v.z + v.w * v.w;
    sq = warp_sum(sq);
    float rn = 1.0f / fmaxf(sqrtf(sq), 1e-12f);
    __nv_bfloat162 lo = __floats2bfloat162_rn(v.x * rn, v.y * rn);
    __nv_bfloat162 hi = __floats2bfloat162_rn(v.z * rn, v.w * rn);
    uint2 u;
    u.x = *reinterpret_cast<uint32_t*>(&lo);
    u.y = *reinterpret_cast<uint32_t*>(&hi);
    dst[lane] = u;
}

// ------------------------- positive term (full fp32) ------------------------
__global__ void pos_kernel(const float* __restrict__ xs,
                           const int* __restrict__ ys32,
                           const float* __restrict__ proxies) {
    int warp = (blockIdx.x * blockDim.x + threadIdx.x) >> 5;   // = b
    int lane = threadIdx.x & 31;
    if (warp >= B_ROWS) return;
    int y = g_is64 ? ys32[2 * warp] : ys32[warp];
    float4 xv = reinterpret_cast<const float4*>(xs + (size_t)warp * D_DIM)[lane];
    float4 pv = reinterpret_cast<const float4*>(proxies + (size_t)y * D_DIM)[lane];
    float xsq = xv.x * xv.x + xv.y * xv.y + xv.z * xv.z + xv.w * xv.w;
    float psq = pv.x * pv.x + pv.y * pv.y + pv.z * pv.z + pv.w * pv.w;
    float xp  = xv.x * pv.x + xv.y * pv.y + xv.z * pv.z + xv.w * pv.w;
    xsq = warp_sum(xsq);
    psq = warp_sum(psq);
    xp  = warp_sum(xp);
    if (lane == 0) {
        float norm = fmaxf(sqrtf(psq), 1e-12f);
        float d = xsq + 1.0f - 2.0f * xp / norm;
        g_dpos[warp] = d;
        g_xsq[warp]  = xsq;
    }
}

// ------------------------- main GEMM + exp row-sum epilogue -----------------
__global__ __launch_bounds__(256) void gemm_kernel() {
    extern __shared__ __align__(16) char smem_raw[];
    __nv_bfloat16* sA = reinterpret_cast<__nv_bfloat16*>(smem_raw);
    __nv_bfloat16* sB = sA + BM * LDS_A;

    const int tid   = threadIdx.x;
    const int mbase = blockIdx.y * BM;
    const int nbase = blockIdx.x * BN;

    // --- load A tile (128x128 bf16) and B tile (128x128 bf16), int4 copies ---
    {
        const int4* gA = reinterpret_cast<const int4*>(g_X + (size_t)mbase * D_DIM);
        const int4* gB = reinterpret_cast<const int4*>(g_P + (size_t)nbase * D_DIM);
        int c  = tid & 15;      // int4 column (16 per row)
        int r0 = tid >> 4;      // rows 0..15
#pragma unroll
        for (int i = 0; i < 8; i++) {
            int r = r0 + i * 16;
            *reinterpret_cast<int4*>(&sA[r * LDS_A + c * 8]) = gA[r * 16 + c];
            *reinterpret_cast<int4*>(&sB[r * LDS_A + c * 8]) = gB[r * 16 + c];
        }
    }
    __syncthreads();

    const int warp = tid >> 5;
    const int lane = tid & 31;
    const int mrow = warp * 16;              // warp owns rows [mrow, mrow+16)

    float acc[16][4];
#pragma unroll
    for (int f = 0; f < 16; f++)
#pragma unroll
        for (int j = 0; j < 4; j++) acc[f][j] = 0.0f;

    // A frag address pattern: lanes 0-15 -> rows, lanes 16-31 -> +8 k-cols
    const int aRow = mrow + (lane & 15);
    const int aColOff = (lane >> 4) * 8;
    // B frag address pattern (x4 = two n-frags):
    const int bRowOff = (lane & 7) + ((lane >> 4) << 3);
    const int bColOff = ((lane >> 3) & 1) * 8;

#pragma unroll
    for (int k = 0; k < 8; k++) {
        const int kk = k * 16;
        uint32_t a0, a1, a2, a3;
        {
            uint32_t addrA = (uint32_t)__cvta_generic_to_shared(
                &sA[aRow * LDS_A + kk + aColOff]);
            asm volatile(
                "ldmatrix.sync.aligned.m8n8.x4.shared.b16 {%0,%1,%2,%3}, [%4];\n"
                : "=r"(a0), "=r"(a1), "=r"(a2), "=r"(a3) : "r"(addrA));
        }
#pragma unroll
        for (int nf = 0; nf < 8; nf++) {
            uint32_t b0, b1, b2, b3;
            uint32_t addrB = (uint32_t)__cvta_generic_to_shared(
                &sB[(nf * 16 + bRowOff) * LDS_A + kk + bColOff]);
            asm volatile(
                "ldmatrix.sync.aligned.m8n8.x4.shared.b16 {%0,%1,%2,%3}, [%4];\n"
                : "=r"(b0), "=r"(b1), "=r"(b2), "=r"(b3) : "r"(addrB));
            int f = 2 * nf;
            asm volatile(
                "mma.sync.aligned.m16n8k16.row.col.f32.bf16.bf16.f32 "
                "{%0,%1,%2,%3}, {%4,%5,%6,%7}, {%8,%9}, {%0,%1,%2,%3};\n"
                : "+f"(acc[f][0]), "+f"(acc[f][1]), "+f"(acc[f][2]), "+f"(acc[f][3])
                : "r"(a0), "r"(a1), "r"(a2), "r"(a3), "r"(b0), "r"(b1));
            asm volatile(
                "mma.sync.aligned.m16n8k16.row.col.f32.bf16.bf16.f32 "
                "{%0,%1,%2,%3}, {%4,%5,%6,%7}, {%8,%9}, {%0,%1,%2,%3};\n"
                : "+f"(acc[f+1][0]), "+f"(acc[f+1][1]), "+f"(acc[f+1][2]), "+f"(acc[f+1][3])
                : "r"(a0), "r"(a1), "r"(a2), "r"(a3), "r"(b2), "r"(b3));
        }
    }

    // --- epilogue: e = exp(2*dot), masked row sums -> deterministic partials
    float sum0 = 0.0f, sum1 = 0.0f;
#pragma unroll
    for (int f = 0; f < 16; f++) {
        int n0 = nbase + f * 8 + (lane & 3) * 2;   // even; n0+1 valid iff n0 valid
        if (n0 < C_CLS) {
            sum0 += __expf(2.0f * acc[f][0]) + __expf(2.0f * acc[f][1]);
            sum1 += __expf(2.0f * acc[f][2]) + __expf(2.0f * acc[f][3]);
        }
    }
    // reduce over the 4 lanes sharing a row (lane&3)
    sum0 += __shfl_xor_sync(0xFFFFFFFFu, sum0, 1);
    sum0 += __shfl_xor_sync(0xFFFFFFFFu, sum0, 2);
    sum1 += __shfl_xor_sync(0xFFFFFFFFu, sum1, 1);
    sum1 += __shfl_xor_sync(0xFFFFFFFFu, sum1, 2);
    if ((lane & 3) == 0) {
        int r = mbase + mrow + (lane >> 2);
        g_partial[blockIdx.x][r]     = sum0;
        g_partial[blockIdx.x][r + 8] = sum1;
    }
}

// ------------------------- final reduce --------------------------------------
__global__ void final_kernel(float* __restrict__ out) {
    __shared__ float red[1024];
    int b = threadIdx.x;
    float S = 0.0f;
    for (int t = 0; t < NTILES; t++) S += g_partial[t][b];
    float d   = g_dpos[b];
    float xsq = g_xsq[b];
    float neg = expf(-xsq - 1.0f) * S - expf(-d);
    red[b] = d + logf(neg);
    __syncthreads();
    for (int s = 512; s > 0; s >>= 1) {
        if (b < s) red[b] += red[b + s];
        __syncthreads();
    }
    if (b == 0) out[0] = red[0] * (1.0f / (float)B_ROWS);
}

// ------------------------- launch ---------------------------------------------
extern "C" void kernel_launch(void* const* d_in, const int* in_sizes, int n_in,
                              void* d_out, int out_size) {
    // identify inputs by element count (robust to metadata ordering)
    const float* xs = nullptr;
    const int*   ys = nullptr;
    const float* proxies = nullptr;
    for (int i = 0; i < n_in; i++) {
        if (in_sizes[i] == B_ROWS)                ys      = (const int*)d_in[i];
        else if (in_sizes[i] == B_ROWS * D_DIM)   xs      = (const float*)d_in[i];
        else if (in_sizes[i] == C_CLS * D_DIM)    proxies = (const float*)d_in[i];
    }
    float* out = (float*)d_out;

    cudaFuncSetAttribute(gemm_kernel,
                         cudaFuncAttributeMaxDynamicSharedMemorySize, SMEM_BYTES);

    detect_kernel<<<1, 512>>>(ys);
    convertx_kernel<<<(B_ROWS * D_DIM / 4) / 256, 256>>>(xs);
    normp_kernel<<<N_PAD / 8, 256>>>(proxies);
    pos_kernel<<<(B_ROWS * 32) / 256, 256>>>(xs, ys, proxies);
    gemm_kernel<<<dim3(NTILES, B_ROWS / BM), 256, SMEM_BYTES>>>();
    final_kernel<<<1, 1024>>>(out);
}

// round 3
// speedup vs baseline: 1.0224x; 1.0224x over previous
#include <cuda_runtime.h>
#include <cuda_bf16.h>
#include <cstdint>

// ---------------------------------------------------------------------------
// ProxyNCALoss on GB300 (sm_103a-build-limited-to-sm_103 ISA) — HMMA version.
//   loss_b = d_pos[b] + log( exp(-xsq_b - 1) * (S_b - 96) - exp(-d_pos_b) )
//   S_b    = sum over padded classes of exp(2 * dot(x_b, p_hat_c))
// GEMM M=1024, N=100096 (782 tiles x 128), K=128 bf16 mma.sync.
// One CTA per N-tile: B tile normalized fp32->bf16 into SMEM once, then loops
// all 8 M-tiles with cp.async double-buffered A and fused exp row-sum epilogue.
// ---------------------------------------------------------------------------

#define C_CLS 100000
#define D_DIM 128
#define B_ROWS 1024

constexpr int BM = 128;
constexpr int BN = 128;
constexpr int NTILES = (C_CLS + BN - 1) / BN;   // 782
constexpr int N_PADS = NTILES * BN - C_CLS;     // 96
constexpr int M_ITERS = B_ROWS / BM;            // 8

constexpr int LDS = 136;                        // bf16 elems per smem row (pad 8)
constexpr int A_TILE_B = BM * LDS * 2;          // 34816
constexpr int B_TILE_B = BN * LDS * 2;          // 34816
constexpr int SMEM_B_OFF = 2 * A_TILE_B;        // A double buffer first
constexpr int SMEM_TOTAL = SMEM_B_OFF + B_TILE_B;  // 104448

// ------------------------- device scratch ----------------------------------
__device__ __nv_bfloat16 g_X[B_ROWS * D_DIM];
__device__ float g_partA[(size_t)NTILES * B_ROWS];   // cols 0-63 of each tile
__device__ float g_partB[(size_t)NTILES * B_ROWS];   // cols 64-127
__device__ float g_dpos[B_ROWS];
__device__ float g_xsq[B_ROWS];
__device__ int   g_is64;

// ------------------------- helpers -----------------------------------------
__device__ __forceinline__ float warp_sum(float v) {
#pragma unroll
    for (int m = 16; m > 0; m >>= 1) v += __shfl_xor_sync(0xFFFFFFFFu, v, m);
    return v;
}
__device__ __forceinline__ void cp_async16(uint32_t dst, const void* src) {
    asm volatile("cp.async.cg.shared.global [%0], [%1], 16;" :: "r"(dst), "l"(src));
}
#define CP_COMMIT() asm volatile("cp.async.commit_group;" ::: "memory")
#define CP_WAIT1()  asm volatile("cp.async.wait_group 1;" ::: "memory")
#define CP_WAIT0()  asm volatile("cp.async.wait_group 0;" ::: "memory")

#define LDSM_X4(r0, r1, r2, r3, addr) \
    asm volatile("ldmatrix.sync.aligned.m8n8.x4.shared.b16 {%0,%1,%2,%3}, [%4];\n" \
                 : "=r"(r0), "=r"(r1), "=r"(r2), "=r"(r3) : "r"(addr))

#define MMA16816(acc, a0, a1, a2, a3, b0, b1) \
    asm volatile("mma.sync.aligned.m16n8k16.row.col.f32.bf16.bf16.f32 " \
                 "{%0,%1,%2,%3}, {%4,%5,%6,%7}, {%8,%9}, {%0,%1,%2,%3};\n" \
                 : "+f"((acc)[0]), "+f"((acc)[1]), "+f"((acc)[2]), "+f"((acc)[3]) \
                 : "r"(a0), "r"(a1), "r"(a2), "r"(a3), "r"(b0), "r"(b1))

// ------------------------- small kernels ------------------------------------
__global__ void detect_kernel(const int* __restrict__ ys32) {
    __shared__ int flag;
    if (threadIdx.x == 0) flag = 1;
    __syncthreads();
    if (ys32[2 * threadIdx.x + 1] != 0) flag = 0;   // int64 labels => odd words 0
    __syncthreads();
    if (threadIdx.x == 0) g_is64 = flag;
}

__global__ void convertx_kernel(const float* __restrict__ xs) {
    int i = blockIdx.x * blockDim.x + threadIdx.x;
    float4 v = reinterpret_cast<const float4*>(xs)[i];
    __nv_bfloat162 lo = __floats2bfloat162_rn(v.x, v.y);
    __nv_bfloat162 hi = __floats2bfloat162_rn(v.z, v.w);
    reinterpret_cast<__nv_bfloat162*>(g_X)[2 * i]     = lo;
    reinterpret_cast<__nv_bfloat162*>(g_X)[2 * i + 1] = hi;
}

__global__ void pos_kernel(const float* __restrict__ xs,
                           const int* __restrict__ ys32,
                           const float* __restrict__ proxies) {
    int warp = (blockIdx.x * blockDim.x + threadIdx.x) >> 5;
    int lane = threadIdx.x & 31;
    if (warp >= B_ROWS) return;
    int y = g_is64 ? ys32[2 * warp] : ys32[warp];
    float4 xv = reinterpret_cast<const float4*>(xs + (size_t)warp * D_DIM)[lane];
    float4 pv = reinterpret_cast<const float4*>(proxies + (size_t)y * D_DIM)[lane];
    float xsq = xv.x*xv.x + xv.y*xv.y + xv.z*xv.z + xv.w*xv.w;
    float psq = pv.x*pv.x + pv.y*pv.y + pv.z*pv.z + pv.w*pv.w;
    float xp  = xv.x*pv.x + xv.y*pv.y + xv.z*pv.z + xv.w*pv.w;
    xsq = warp_sum(xsq); psq = warp_sum(psq); xp = warp_sum(xp);
    if (lane == 0) {
        float norm = fmaxf(sqrtf(psq), 1e-12f);
        g_dpos[warp] = xsq + 1.0f - 2.0f * xp / norm;
        g_xsq[warp]  = xsq;
    }
}

// ------------------------- GEMM + exp row-sum -------------------------------
__global__ __launch_bounds__(256, 2) void gemm_kernel(const float* __restrict__ proxies) {
    extern __shared__ __align__(16) char smem[];
    __nv_bfloat16* sB = reinterpret_cast<__nv_bfloat16*>(smem + SMEM_B_OFF);
    const uint32_t sbase = (uint32_t)__cvta_generic_to_shared(smem);

    const int tid  = threadIdx.x;
    const int wid  = tid >> 5;
    const int lane = tid & 31;
    const int nt    = blockIdx.x;
    const int nbase = nt * BN;

    // ---- start A tile 0 load immediately ----
    {
        const char* gA = reinterpret_cast<const char*>(g_X);
#pragma unroll
        for (int j = 0; j < 8; j++) {
            int idx = tid + 256 * j;
            int r = idx >> 4, c8 = idx & 15;
            cp_async16(sbase + r * (LDS * 2) + c8 * 16, gA + r * 256 + c8 * 16);
        }
        CP_COMMIT();
    }

    // ---- B tile: load fp32 proxies, L2-normalize, bf16, into SMEM ----
    {
#pragma unroll 2
        for (int i = 0; i < 16; i++) {
            const int r  = wid * 16 + i;
            const int gr = nbase + r;
            float4 v;
            if (gr < C_CLS) v = reinterpret_cast<const float4*>(proxies + (size_t)gr * D_DIM)[lane];
            else            v = make_float4(0.f, 0.f, 0.f, 0.f);
            float sq = warp_sum(v.x*v.x + v.y*v.y + v.z*v.z + v.w*v.w);
            float rn = rsqrtf(fmaxf(sq, 1e-24f));
            if (gr >= C_CLS) rn = 0.0f;
            __nv_bfloat162 lo = __floats2bfloat162_rn(v.x * rn, v.y * rn);
            __nv_bfloat162 hi = __floats2bfloat162_rn(v.z * rn, v.w * rn);
            uint2 u;
            u.x = *reinterpret_cast<uint32_t*>(&lo);
            u.y = *reinterpret_cast<uint32_t*>(&hi);
            *reinterpret_cast<uint2*>(&sB[r * LDS + lane * 4]) = u;
        }
    }

    // warp tiling: 4 (M) x 2 (N); warp tile 32 rows x 64 cols
    const int mrow  = (wid >> 1) * 32;
    const int nwarp = wid & 1;
    const int ncb   = nwarp * 64;
    float* gpart = (nwarp ? g_partB : g_partA) + (size_t)nt * B_ROWS;

    // ldmatrix address components
    const int aLane   = (lane & 15);
    const int aColOff = (lane >> 4) * 8;
    const int bRowOff = (lane & 7) + ((lane >> 4) << 3);
    const int bColOff = ((lane >> 3) & 1) * 8;

#pragma unroll 1
    for (int it = 0; it < M_ITERS; it++) {
        const int buf = it & 1;
        if (it + 1 < M_ITERS) {
            const char* gA = reinterpret_cast<const char*>(g_X) + (size_t)(it + 1) * BM * D_DIM * 2;
            const uint32_t dbase = sbase + (buf ^ 1) * A_TILE_B;
#pragma unroll
            for (int j = 0; j < 8; j++) {
                int idx = tid + 256 * j;
                int r = idx >> 4, c8 = idx & 15;
                cp_async16(dbase + r * (LDS * 2) + c8 * 16, gA + r * 256 + c8 * 16);
            }
            CP_COMMIT();
            CP_WAIT1();
        } else {
            CP_WAIT0();
        }
        __syncthreads();

        const __nv_bfloat16* sA = reinterpret_cast<const __nv_bfloat16*>(smem + buf * A_TILE_B);

        float acc[2][8][4];
#pragma unroll
        for (int mf = 0; mf < 2; mf++)
#pragma unroll
            for (int nf = 0; nf < 8; nf++)
#pragma unroll
                for (int j = 0; j < 4; j++) acc[mf][nf][j] = 0.0f;

#pragma unroll
        for (int k = 0; k < 8; k++) {
            const int kk = k * 16;
            uint32_t a[2][4];
#pragma unroll
            for (int mf = 0; mf < 2; mf++) {
                uint32_t addrA = (uint32_t)__cvta_generic_to_shared(
                    &sA[(mrow + mf * 16 + aLane) * LDS + kk + aColOff]);
                LDSM_X4(a[mf][0], a[mf][1], a[mf][2], a[mf][3], addrA);
            }
#pragma unroll
            for (int g = 0; g < 4; g++) {
                uint32_t b0, b1, b2, b3;
                uint32_t addrB = (uint32_t)__cvta_generic_to_shared(
                    &sB[(ncb + g * 16 + bRowOff) * LDS + kk + bColOff]);
                LDSM_X4(b0, b1, b2, b3, addrB);
#pragma unroll
                for (int mf = 0; mf < 2; mf++) {
                    MMA16816(acc[mf][2 * g],     a[mf][0], a[mf][1], a[mf][2], a[mf][3], b0, b1);
                    MMA16816(acc[mf][2 * g + 1], a[mf][0], a[mf][1], a[mf][2], a[mf][3], b2, b3);
                }
            }
        }

        // ---- epilogue: exp(2*dot) row sums over this warp's 64 cols ----
#pragma unroll
        for (int mf = 0; mf < 2; mf++) {
            float s0 = 0.0f, s1 = 0.0f;
#pragma unroll
            for (int nf = 0; nf < 8; nf++) {
                s0 += __expf(2.0f * acc[mf][nf][0]) + __expf(2.0f * acc[mf][nf][1]);
                s1 += __expf(2.0f * acc[mf][nf][2]) + __expf(2.0f * acc[mf][nf][3]);
            }
            s0 += __shfl_xor_sync(0xFFFFFFFFu, s0, 1);
            s0 += __shfl_xor_sync(0xFFFFFFFFu, s0, 2);
            s1 += __shfl_xor_sync(0xFFFFFFFFu, s1, 1);
            s1 += __shfl_xor_sync(0xFFFFFFFFu, s1, 2);
            if ((lane & 3) == 0) {
                int r = it * BM + mrow + mf * 16 + (lane >> 2);
                gpart[r]     = s0;
                gpart[r + 8] = s1;
            }
        }
        __syncthreads();
    }
}

// ------------------------- final reduce ------------------------------------
__global__ void final_kernel(float* __restrict__ out) {
    __shared__ float red[1024];
    int b = threadIdx.x;
    float S = 0.0f;
    for (int t = 0; t < NTILES; t++)
        S += g_partA[(size_t)t * B_ROWS + b] + g_partB[(size_t)t * B_ROWS + b];
    S -= (float)N_PADS;                     // zero-pad rows contribute exp(0)=1
    float d   = g_dpos[b];
    float xsq = g_xsq[b];
    float neg = expf(-xsq - 1.0f) * S - expf(-d);
    red[b] = d + logf(neg);
    __syncthreads();
    for (int s = 512; s > 0; s >>= 1) {
        if (b < s) red[b] += red[b + s];
        __syncthreads();
    }
    if (b == 0) out[0] = red[0] * (1.0f / (float)B_ROWS);
}

// ------------------------- launch -------------------------------------------
extern "C" void kernel_launch(void* const* d_in, const int* in_sizes, int n_in,
                              void* d_out, int out_size) {
    const float* xs = nullptr;
    const int*   ys = nullptr;
    const float* proxies = nullptr;
    for (int i = 0; i < n_in; i++) {
        if (in_sizes[i] == B_ROWS)              ys      = (const int*)d_in[i];
        else if (in_sizes[i] == B_ROWS * D_DIM) xs      = (const float*)d_in[i];
        else if (in_sizes[i] == C_CLS * D_DIM)  proxies = (const float*)d_in[i];
    }
    float* out = (float*)d_out;

    cudaFuncSetAttribute(gemm_kernel,
                         cudaFuncAttributeMaxDynamicSharedMemorySize, SMEM_TOTAL);

    detect_kernel<<<1, 512>>>(ys);
    convertx_kernel<<<(B_ROWS * D_DIM / 4) / 256, 256>>>(xs);
    pos_kernel<<<(B_ROWS * 32) / 256, 256>>>(xs, ys, proxies);
    gemm_kernel<<<NTILES, 256, SMEM_TOTAL>>>(proxies);
    final_kernel<<<1, 1024>>>(out);
}

// round 4
// speedup vs baseline: 1.2557x; 1.2281x over previous
#include <cuda_runtime.h>
#include <cuda_bf16.h>
#include <cstdint>

// ---------------------------------------------------------------------------
// ProxyNCALoss on GB300 — HMMA path (ptxas stage targets sm_103: no tcgen05).
//   loss_b = d_pos[b] + log( exp(-xsq_b - 1) * (S_b - 96) - exp(-d_pos_b) )
// GEMM M=1024, N=100096 (782 x 128), K=128, bf16 mma.sync.
// R4: 512-thread CTAs (32 warps/SM), fused pre-kernel, parallel final reduce.
// ---------------------------------------------------------------------------

#define C_CLS 100000
#define D_DIM 128
#define B_ROWS 1024

constexpr int BM = 128;
constexpr int BN = 128;
constexpr int NTILES = (C_CLS + BN - 1) / BN;   // 782
constexpr int N_PADS = NTILES * BN - C_CLS;     // 96
constexpr int M_ITERS = B_ROWS / BM;            // 8

constexpr int LDS = 136;                        // bf16 elems per smem row
constexpr int A_TILE_B = BM * LDS * 2;          // 34816
constexpr int B_TILE_B = BN * LDS * 2;          // 34816
constexpr int SMEM_B_OFF = 2 * A_TILE_B;
constexpr int SMEM_TOTAL = SMEM_B_OFF + B_TILE_B;  // 104448

// ------------------------- device scratch ----------------------------------
__device__ __nv_bfloat16 g_X[B_ROWS * D_DIM];
__device__ float g_partA[(size_t)B_ROWS * NTILES];   // [b][tile], cols 0-63
__device__ float g_partB[(size_t)B_ROWS * NTILES];   // [b][tile], cols 64-127
__device__ float g_dpos[B_ROWS];
__device__ float g_xsq[B_ROWS];
__device__ float g_loss[B_ROWS];

// ------------------------- helpers -----------------------------------------
__device__ __forceinline__ float warp_sum(float v) {
#pragma unroll
    for (int m = 16; m > 0; m >>= 1) v += __shfl_xor_sync(0xFFFFFFFFu, v, m);
    return v;
}
__device__ __forceinline__ void cp_async16(uint32_t dst, const void* src) {
    asm volatile("cp.async.cg.shared.global [%0], [%1], 16;" :: "r"(dst), "l"(src));
}
#define CP_COMMIT() asm volatile("cp.async.commit_group;" ::: "memory")
#define CP_WAIT1()  asm volatile("cp.async.wait_group 1;" ::: "memory")
#define CP_WAIT0()  asm volatile("cp.async.wait_group 0;" ::: "memory")

#define LDSM_X4(r0, r1, r2, r3, addr) \
    asm volatile("ldmatrix.sync.aligned.m8n8.x4.shared.b16 {%0,%1,%2,%3}, [%4];\n" \
                 : "=r"(r0), "=r"(r1), "=r"(r2), "=r"(r3) : "r"(addr))

#define MMA16816(acc, a0, a1, a2, a3, b0, b1) \
    asm volatile("mma.sync.aligned.m16n8k16.row.col.f32.bf16.bf16.f32 " \
                 "{%0,%1,%2,%3}, {%4,%5,%6,%7}, {%8,%9}, {%0,%1,%2,%3};\n" \
                 : "+f"((acc)[0]), "+f"((acc)[1]), "+f"((acc)[2]), "+f"((acc)[3]) \
                 : "r"(a0), "r"(a1), "r"(a2), "r"(a3), "r"(b0), "r"(b1))

// ------------------------- fused pre-kernel ---------------------------------
// One warp per batch row b: dtype-detect (ballot), xs->bf16 convert, positive
// term (full fp32).
__global__ void pre_kernel(const float* __restrict__ xs,
                           const int* __restrict__ ys32,
                           const float* __restrict__ proxies) {
    int b    = (blockIdx.x * blockDim.x + threadIdx.x) >> 5;
    int lane = threadIdx.x & 31;
    if (b >= B_ROWS) return;

    // int64-vs-int32 label detection: odd 32-bit words of the first 32 labels
    // are all zero iff int64 (indices <= 63 are safe in both layouts).
    int probe = ys32[2 * lane + 1];
    bool is64 = (__ballot_sync(0xFFFFFFFFu, probe != 0) == 0u);
    int y = is64 ? ys32[2 * b] : ys32[b];

    float4 xv = reinterpret_cast<const float4*>(xs + (size_t)b * D_DIM)[lane];
    float4 pv = reinterpret_cast<const float4*>(proxies + (size_t)y * D_DIM)[lane];

    // xs -> bf16 (reuses the load)
    __nv_bfloat162 lo = __floats2bfloat162_rn(xv.x, xv.y);
    __nv_bfloat162 hi = __floats2bfloat162_rn(xv.z, xv.w);
    uint2 u;
    u.x = *reinterpret_cast<uint32_t*>(&lo);
    u.y = *reinterpret_cast<uint32_t*>(&hi);
    reinterpret_cast<uint2*>(g_X + (size_t)b * D_DIM)[lane] = u;

    float xsq = xv.x*xv.x + xv.y*xv.y + xv.z*xv.z + xv.w*xv.w;
    float psq = pv.x*pv.x + pv.y*pv.y + pv.z*pv.z + pv.w*pv.w;
    float xp  = xv.x*pv.x + xv.y*pv.y + xv.z*pv.z + xv.w*pv.w;
    xsq = warp_sum(xsq); psq = warp_sum(psq); xp = warp_sum(xp);
    if (lane == 0) {
        float norm = fmaxf(sqrtf(psq), 1e-12f);
        g_dpos[b] = xsq + 1.0f - 2.0f * xp / norm;
        g_xsq[b]  = xsq;
    }
}

// ------------------------- GEMM + exp row-sum -------------------------------
__global__ __launch_bounds__(512, 2) void gemm_kernel(const float* __restrict__ proxies) {
    extern __shared__ __align__(16) char smem[];
    __nv_bfloat16* sB = reinterpret_cast<__nv_bfloat16*>(smem + SMEM_B_OFF);
    const uint32_t sbase = (uint32_t)__cvta_generic_to_shared(smem);

    const int tid  = threadIdx.x;
    const int wid  = tid >> 5;
    const int lane = tid & 31;
    const int nt    = blockIdx.x;
    const int nbase = nt * BN;

    // ---- start A tile 0 load immediately ----
    {
        const char* gA = reinterpret_cast<const char*>(g_X);
#pragma unroll
        for (int j = 0; j < 4; j++) {
            int idx = tid + 512 * j;
            int r = idx >> 4, c8 = idx & 15;
            cp_async16(sbase + r * (LDS * 2) + c8 * 16, gA + r * 256 + c8 * 16);
        }
        CP_COMMIT();
    }

    // ---- B tile: load fp32 proxies, L2-normalize, bf16, into SMEM ----
    {
#pragma unroll 2
        for (int i = 0; i < 8; i++) {
            const int r  = wid * 8 + i;
            const int gr = nbase + r;
            float4 v;
            if (gr < C_CLS) v = reinterpret_cast<const float4*>(proxies + (size_t)gr * D_DIM)[lane];
            else            v = make_float4(0.f, 0.f, 0.f, 0.f);
            float sq = warp_sum(v.x*v.x + v.y*v.y + v.z*v.z + v.w*v.w);
            float rn = rsqrtf(fmaxf(sq, 1e-24f));
            if (gr >= C_CLS) rn = 0.0f;
            __nv_bfloat162 lo = __floats2bfloat162_rn(v.x * rn, v.y * rn);
            __nv_bfloat162 hi = __floats2bfloat162_rn(v.z * rn, v.w * rn);
            uint2 u;
            u.x = *reinterpret_cast<uint32_t*>(&lo);
            u.y = *reinterpret_cast<uint32_t*>(&hi);
            *reinterpret_cast<uint2*>(&sB[r * LDS + lane * 4]) = u;
        }
    }

    // 16 warps: 8 (M) x 2 (N); warp tile 16 rows x 64 cols
    const int mrow  = (wid >> 1) * 16;
    const int nwarp = wid & 1;
    const int ncb   = nwarp * 64;
    float* gpart = (nwarp ? g_partB : g_partA);

    const int aLane   = (lane & 15);
    const int aColOff = (lane >> 4) * 8;
    const int bRowOff = (lane & 7) + ((lane >> 4) << 3);
    const int bColOff = ((lane >> 3) & 1) * 8;

#pragma unroll 1
    for (int it = 0; it < M_ITERS; it++) {
        const int buf = it & 1;
        if (it + 1 < M_ITERS) {
            const char* gA = reinterpret_cast<const char*>(g_X) + (size_t)(it + 1) * BM * D_DIM * 2;
            const uint32_t dbase = sbase + (buf ^ 1) * A_TILE_B;
#pragma unroll
            for (int j = 0; j < 4; j++) {
                int idx = tid + 512 * j;
                int r = idx >> 4, c8 = idx & 15;
                cp_async16(dbase + r * (LDS * 2) + c8 * 16, gA + r * 256 + c8 * 16);
            }
            CP_COMMIT();
            CP_WAIT1();
        } else {
            CP_WAIT0();
        }
        __syncthreads();

        const __nv_bfloat16* sA = reinterpret_cast<const __nv_bfloat16*>(smem + buf * A_TILE_B);

        float acc[8][4];
#pragma unroll
        for (int nf = 0; nf < 8; nf++)
#pragma unroll
            for (int j = 0; j < 4; j++) acc[nf][j] = 0.0f;

#pragma unroll
        for (int k = 0; k < 8; k++) {
            const int kk = k * 16;
            uint32_t a0, a1, a2, a3;
            {
                uint32_t addrA = (uint32_t)__cvta_generic_to_shared(
                    &sA[(mrow + aLane) * LDS + kk + aColOff]);
                LDSM_X4(a0, a1, a2, a3, addrA);
            }
#pragma unroll
            for (int g = 0; g < 4; g++) {
                uint32_t b0, b1, b2, b3;
                uint32_t addrB = (uint32_t)__cvta_generic_to_shared(
                    &sB[(ncb + g * 16 + bRowOff) * LDS + kk + bColOff]);
                LDSM_X4(b0, b1, b2, b3, addrB);
                MMA16816(acc[2 * g],     a0, a1, a2, a3, b0, b1);
                MMA16816(acc[2 * g + 1], a0, a1, a2, a3, b2, b3);
            }
        }

        // ---- epilogue: exp(2*dot) row sums over this warp's 64 cols ----
        float s0 = 0.0f, s1 = 0.0f;
#pragma unroll
        for (int nf = 0; nf < 8; nf++) {
            s0 += __expf(2.0f * acc[nf][0]) + __expf(2.0f * acc[nf][1]);
            s1 += __expf(2.0f * acc[nf][2]) + __expf(2.0f * acc[nf][3]);
        }
        s0 += __shfl_xor_sync(0xFFFFFFFFu, s0, 1);
        s0 += __shfl_xor_sync(0xFFFFFFFFu, s0, 2);
        s1 += __shfl_xor_sync(0xFFFFFFFFu, s1, 1);
        s1 += __shfl_xor_sync(0xFFFFFFFFu, s1, 2);
        if ((lane & 3) == 0) {
            int r = it * BM + mrow + (lane >> 2);
            gpart[(size_t)r * NTILES + nt]       = s0;
            gpart[(size_t)(r + 8) * NTILES + nt] = s1;
        }
        __syncthreads();
    }
}

// ------------------------- reduce stage 1: per-row S + loss ----------------
__global__ void reduce1_kernel() {
    __shared__ float red[256];
    const int b = blockIdx.x;
    const int t = threadIdx.x;
    const float* pa = g_partA + (size_t)b * NTILES;
    const float* pb = g_partB + (size_t)b * NTILES;
    float s = 0.0f;
    for (int i = t; i < NTILES; i += 256) s += pa[i] + pb[i];
    red[t] = s;
    __syncthreads();
    for (int k = 128; k > 0; k >>= 1) {
        if (t < k) red[t] += red[t + k];
        __syncthreads();
    }
    if (t == 0) {
        float S = red[0] - (float)N_PADS;     // zero-pad rows contribute exp(0)=1
        float d   = g_dpos[b];
        float xsq = g_xsq[b];
        float neg = expf(-xsq - 1.0f) * S - expf(-d);
        g_loss[b] = d + logf(neg);
    }
}

// ------------------------- reduce stage 2: mean ------------------------------
__global__ void reduce2_kernel(float* __restrict__ out) {
    __shared__ float red[1024];
    int b = threadIdx.x;
    red[b] = g_loss[b];
    __syncthreads();
    for (int s = 512; s > 0; s >>= 1) {
        if (b < s) red[b] += red[b + s];
        __syncthreads();
    }
    if (b == 0) out[0] = red[0] * (1.0f / (float)B_ROWS);
}

// ------------------------- launch -------------------------------------------
extern "C" void kernel_launch(void* const* d_in, const int* in_sizes, int n_in,
                              void* d_out, int out_size) {
    const float* xs = nullptr;
    const int*   ys = nullptr;
    const float* proxies = nullptr;
    for (int i = 0; i < n_in; i++) {
        if (in_sizes[i] == B_ROWS)              ys      = (const int*)d_in[i];
        else if (in_sizes[i] == B_ROWS * D_DIM) xs      = (const float*)d_in[i];
        else if (in_sizes[i] == C_CLS * D_DIM)  proxies = (const float*)d_in[i];
    }
    float* out = (float*)d_out;

    cudaFuncSetAttribute(gemm_kernel,
                         cudaFuncAttributeMaxDynamicSharedMemorySize, SMEM_TOTAL);

    pre_kernel<<<B_ROWS / 8, 256>>>(xs, ys, proxies);
    gemm_kernel<<<NTILES, 512, SMEM_TOTAL>>>(proxies);
    reduce1_kernel<<<B_ROWS, 256>>>();
    reduce2_kernel<<<1, 1024>>>(out);
}

// round 5
// speedup vs baseline: 1.3027x; 1.0374x over previous
#include <cuda_runtime.h>
#include <cuda_bf16.h>
#include <cstdint>

// ---------------------------------------------------------------------------
// ProxyNCALoss on GB300 — HMMA path (ptxas stage targets sm_103: no tcgen05).
//   loss_b = d_pos[b] + log( exp(-xsq_b - 1) * (S_b - 96) - exp(-d_pos_b) )
// GEMM M=1024, N=100096 (782 x 128), K=128, bf16 mma.sync.
// R5: single-sync mainloop, MLP-8 B-normalization prologue, fused last-block
// reduce (3 launches total).
// ---------------------------------------------------------------------------

#define C_CLS 100000
#define D_DIM 128
#define B_ROWS 1024

constexpr int BM = 128;
constexpr int BN = 128;
constexpr int NTILES = (C_CLS + BN - 1) / BN;   // 782
constexpr int N_PADS = NTILES * BN - C_CLS;     // 96
constexpr int M_ITERS = B_ROWS / BM;            // 8

constexpr int LDS = 136;                        // bf16 elems per smem row
constexpr int A_TILE_B = BM * LDS * 2;          // 34816
constexpr int B_TILE_B = BN * LDS * 2;          // 34816
constexpr int SMEM_B_OFF = 2 * A_TILE_B;
constexpr int SMEM_TOTAL = SMEM_B_OFF + B_TILE_B;  // 104448 (2 CTAs/SM)

// ------------------------- device scratch ----------------------------------
__device__ __nv_bfloat16 g_X[B_ROWS * D_DIM];
__device__ float g_partA[(size_t)B_ROWS * NTILES];   // [b][tile], cols 0-63
__device__ float g_partB[(size_t)B_ROWS * NTILES];   // [b][tile], cols 64-127
__device__ float g_dpos[B_ROWS];
__device__ float g_xsq[B_ROWS];
__device__ float g_loss[B_ROWS];
__device__ int   g_cnt;

// ------------------------- helpers -----------------------------------------
__device__ __forceinline__ float warp_sum(float v) {
#pragma unroll
    for (int m = 16; m > 0; m >>= 1) v += __shfl_xor_sync(0xFFFFFFFFu, v, m);
    return v;
}
__device__ __forceinline__ void cp_async16(uint32_t dst, const void* src) {
    asm volatile("cp.async.cg.shared.global [%0], [%1], 16;" :: "r"(dst), "l"(src));
}
#define CP_COMMIT() asm volatile("cp.async.commit_group;" ::: "memory")
#define CP_WAIT0()  asm volatile("cp.async.wait_group 0;" ::: "memory")

#define LDSM_X4(r0, r1, r2, r3, addr) \
    asm volatile("ldmatrix.sync.aligned.m8n8.x4.shared.b16 {%0,%1,%2,%3}, [%4];\n" \
                 : "=r"(r0), "=r"(r1), "=r"(r2), "=r"(r3) : "r"(addr))

#define MMA16816(acc, a0, a1, a2, a3, b0, b1) \
    asm volatile("mma.sync.aligned.m16n8k16.row.col.f32.bf16.bf16.f32 " \
                 "{%0,%1,%2,%3}, {%4,%5,%6,%7}, {%8,%9}, {%0,%1,%2,%3};\n" \
                 : "+f"((acc)[0]), "+f"((acc)[1]), "+f"((acc)[2]), "+f"((acc)[3]) \
                 : "r"(a0), "r"(a1), "r"(a2), "r"(a3), "r"(b0), "r"(b1))

// ------------------------- fused pre-kernel ---------------------------------
__global__ void pre_kernel(const float* __restrict__ xs,
                           const int* __restrict__ ys32,
                           const float* __restrict__ proxies) {
    if (blockIdx.x == 0 && threadIdx.x == 0) g_cnt = 0;   // reset reduce counter

    int b    = (blockIdx.x * blockDim.x + threadIdx.x) >> 5;
    int lane = threadIdx.x & 31;
    if (b >= B_ROWS) return;

    // int64-vs-int32 label detection: odd 32-bit words of the first 32 labels
    // are all zero iff int64.
    int probe = ys32[2 * lane + 1];
    bool is64 = (__ballot_sync(0xFFFFFFFFu, probe != 0) == 0u);
    int y = is64 ? ys32[2 * b] : ys32[b];

    float4 xv = reinterpret_cast<const float4*>(xs + (size_t)b * D_DIM)[lane];
    float4 pv = reinterpret_cast<const float4*>(proxies + (size_t)y * D_DIM)[lane];

    __nv_bfloat162 lo = __floats2bfloat162_rn(xv.x, xv.y);
    __nv_bfloat162 hi = __floats2bfloat162_rn(xv.z, xv.w);
    uint2 u;
    u.x = *reinterpret_cast<uint32_t*>(&lo);
    u.y = *reinterpret_cast<uint32_t*>(&hi);
    reinterpret_cast<uint2*>(g_X + (size_t)b * D_DIM)[lane] = u;

    float xsq = xv.x*xv.x + xv.y*xv.y + xv.z*xv.z + xv.w*xv.w;
    float psq = pv.x*pv.x + pv.y*pv.y + pv.z*pv.z + pv.w*pv.w;
    float xp  = xv.x*pv.x + xv.y*pv.y + xv.z*pv.z + xv.w*pv.w;
    xsq = warp_sum(xsq); psq = warp_sum(psq); xp = warp_sum(xp);
    if (lane == 0) {
        float norm = fmaxf(sqrtf(psq), 1e-12f);
        g_dpos[b] = xsq + 1.0f - 2.0f * xp / norm;
        g_xsq[b]  = xsq;
    }
}

// ------------------------- GEMM + exp row-sum -------------------------------
__global__ __launch_bounds__(512, 2) void gemm_kernel(const float* __restrict__ proxies) {
    extern __shared__ __align__(16) char smem[];
    __nv_bfloat16* sB = reinterpret_cast<__nv_bfloat16*>(smem + SMEM_B_OFF);
    const uint32_t sbase = (uint32_t)__cvta_generic_to_shared(smem);

    const int tid  = threadIdx.x;
    const int wid  = tid >> 5;
    const int lane = tid & 31;
    const int nt    = blockIdx.x;
    const int nbase = nt * BN;

    // ---- start A tile 0 load immediately ----
    {
        const char* gA = reinterpret_cast<const char*>(g_X);
#pragma unroll
        for (int j = 0; j < 4; j++) {
            int idx = tid + 512 * j;
            int r = idx >> 4, c8 = idx & 15;
            cp_async16(sbase + r * (LDS * 2) + c8 * 16, gA + r * 256 + c8 * 16);
        }
        CP_COMMIT();
    }

    // ---- B tile: batched loads (MLP=8), L2-normalize, bf16, into SMEM ----
    {
        const int r0 = wid * 8;
        float4 v[8];
#pragma unroll
        for (int i = 0; i < 8; i++) {
            const int gr = nbase + r0 + i;
            if (gr < C_CLS) v[i] = reinterpret_cast<const float4*>(proxies + (size_t)gr * D_DIM)[lane];
            else            v[i] = make_float4(0.f, 0.f, 0.f, 0.f);
        }
#pragma unroll
        for (int i = 0; i < 8; i++) {
            const int gr = nbase + r0 + i;
            float sq = warp_sum(v[i].x*v[i].x + v[i].y*v[i].y + v[i].z*v[i].z + v[i].w*v[i].w);
            float rn = rsqrtf(fmaxf(sq, 1e-24f));
            if (gr >= C_CLS) rn = 0.0f;
            __nv_bfloat162 lo = __floats2bfloat162_rn(v[i].x * rn, v[i].y * rn);
            __nv_bfloat162 hi = __floats2bfloat162_rn(v[i].z * rn, v[i].w * rn);
            uint2 u;
            u.x = *reinterpret_cast<uint32_t*>(&lo);
            u.y = *reinterpret_cast<uint32_t*>(&hi);
            *reinterpret_cast<uint2*>(&sB[(r0 + i) * LDS + lane * 4]) = u;
        }
    }
    CP_WAIT0();
    __syncthreads();      // A0 complete+visible, B ready

    // 16 warps: 8 (M) x 2 (N); warp tile 16 rows x 64 cols
    const int mrow  = (wid >> 1) * 16;
    const int nwarp = wid & 1;
    const int ncb   = nwarp * 64;
    float* gpart = (nwarp ? g_partB : g_partA);

    const int aLane   = (lane & 15);
    const int aColOff = (lane >> 4) * 8;
    const int bRowOff = (lane & 7) + ((lane >> 4) << 3);
    const int bColOff = ((lane >> 3) & 1) * 8;

#pragma unroll 1
    for (int it = 0; it < M_ITERS; it++) {
        const int buf = it & 1;
        // prefetch A(it+1) into buf^1 — safe: all readers of buf^1 (iter it-1)
        // passed the single sync at the end of it-1.
        if (it + 1 < M_ITERS) {
            const char* gA = reinterpret_cast<const char*>(g_X) + (size_t)(it + 1) * BM * D_DIM * 2;
            const uint32_t dbase = sbase + (buf ^ 1) * A_TILE_B;
#pragma unroll
            for (int j = 0; j < 4; j++) {
                int idx = tid + 512 * j;
                int r = idx >> 4, c8 = idx & 15;
                cp_async16(dbase + r * (LDS * 2) + c8 * 16, gA + r * 256 + c8 * 16);
            }
            CP_COMMIT();
        }

        const __nv_bfloat16* sA = reinterpret_cast<const __nv_bfloat16*>(smem + buf * A_TILE_B);

        float acc[8][4];
#pragma unroll
        for (int nf = 0; nf < 8; nf++)
#pragma unroll
            for (int j = 0; j < 4; j++) acc[nf][j] = 0.0f;

#pragma unroll
        for (int k = 0; k < 8; k++) {
            const int kk = k * 16;
            uint32_t a0, a1, a2, a3;
            {
                uint32_t addrA = (uint32_t)__cvta_generic_to_shared(
                    &sA[(mrow + aLane) * LDS + kk + aColOff]);
                LDSM_X4(a0, a1, a2, a3, addrA);
            }
#pragma unroll
            for (int g = 0; g < 4; g++) {
                uint32_t b0, b1, b2, b3;
                uint32_t addrB = (uint32_t)__cvta_generic_to_shared(
                    &sB[(ncb + g * 16 + bRowOff) * LDS + kk + bColOff]);
                LDSM_X4(b0, b1, b2, b3, addrB);
                MMA16816(acc[2 * g],     a0, a1, a2, a3, b0, b1);
                MMA16816(acc[2 * g + 1], a0, a1, a2, a3, b2, b3);
            }
        }

        // ---- epilogue: exp(2*dot) row sums over this warp's 64 cols ----
        float s0 = 0.0f, s1 = 0.0f;
#pragma unroll
        for (int nf = 0; nf < 8; nf++) {
            s0 += __expf(2.0f * acc[nf][0]) + __expf(2.0f * acc[nf][1]);
            s1 += __expf(2.0f * acc[nf][2]) + __expf(2.0f * acc[nf][3]);
        }
        s0 += __shfl_xor_sync(0xFFFFFFFFu, s0, 1);
        s0 += __shfl_xor_sync(0xFFFFFFFFu, s0, 2);
        s1 += __shfl_xor_sync(0xFFFFFFFFu, s1, 1);
        s1 += __shfl_xor_sync(0xFFFFFFFFu, s1, 2);
        if ((lane & 3) == 0) {
            int r = it * BM + mrow + (lane >> 2);
            gpart[(size_t)r * NTILES + nt]       = s0;
            gpart[(size_t)(r + 8) * NTILES + nt] = s1;
        }

        CP_WAIT0();        // A(it+1) landed (overlapped with k-loop + epilogue)
        __syncthreads();   // single barrier: visibility + buffer ownership
    }
}

// ------------------------- fused reduce (last-block pattern) ----------------
__global__ void reduce_kernel(float* __restrict__ out) {
    __shared__ float red[256];
    __shared__ int   is_last;
    const int b = blockIdx.x;
    const int t = threadIdx.x;
    const float* pa = g_partA + (size_t)b * NTILES;
    const float* pb = g_partB + (size_t)b * NTILES;
    float s = 0.0f;
    for (int i = t; i < NTILES; i += 256) s += pa[i] + pb[i];
    red[t] = s;
    __syncthreads();
    for (int k = 128; k > 0; k >>= 1) {
        if (t < k) red[t] += red[t + k];
        __syncthreads();
    }
    if (t == 0) {
        float S = red[0] - (float)N_PADS;     // zero-pad rows contribute exp(0)=1
        float d   = g_dpos[b];
        float xsq = g_xsq[b];
        float neg = expf(-xsq - 1.0f) * S - expf(-d);
        g_loss[b] = d + logf(neg);
        __threadfence();
        int old = atomicAdd(&g_cnt, 1);
        is_last = (old == B_ROWS - 1);
    }
    __syncthreads();
    if (is_last) {
        // deterministic final reduce over 1024 per-row losses
        float v = g_loss[t] + g_loss[t + 256] + g_loss[t + 512] + g_loss[t + 768];
        red[t] = v;
        __syncthreads();
        for (int k = 128; k > 0; k >>= 1) {
            if (t < k) red[t] += red[t + k];
            __syncthreads();
        }
        if (t == 0) out[0] = red[0] * (1.0f / (float)B_ROWS);
    }
}

// ------------------------- launch -------------------------------------------
extern "C" void kernel_launch(void* const* d_in, const int* in_sizes, int n_in,
                              void* d_out, int out_size) {
    const float* xs = nullptr;
    const int*   ys = nullptr;
    const float* proxies = nullptr;
    for (int i = 0; i < n_in; i++) {
        if (in_sizes[i] == B_ROWS)              ys      = (const int*)d_in[i];
        else if (in_sizes[i] == B_ROWS * D_DIM) xs      = (const float*)d_in[i];
        else if (in_sizes[i] == C_CLS * D_DIM)  proxies = (const float*)d_in[i];
    }
    float* out = (float*)d_out;

    cudaFuncSetAttribute(gemm_kernel,
                         cudaFuncAttributeMaxDynamicSharedMemorySize, SMEM_TOTAL);

    pre_kernel<<<B_ROWS / 8, 256>>>(xs, ys, proxies);
    gemm_kernel<<<NTILES, 512, SMEM_TOTAL>>>(proxies);
    reduce_kernel<<<B_ROWS, 256>>>(out);
}